// round 1
// baseline (speedup 1.0000x reference)
#include <cuda_runtime.h>
#include <cstdint>

#define BATCH 256
#define DLAT  32
#define HID   512
#define GENES 4000
#define NCH   8
#define GC    500      // genes per chunk (8*500 = 4000)
#define GT    512      // g slots per block (4 per thread * 128 threads)
#define NT    128

// Deterministic partial-Gram buffer: [chunk][batch][32*32]
__device__ float g_gramPart[(size_t)NCH * BATCH * DLAT * DLAT];
__device__ float g_lossb[BATCH];

// ---------------------------------------------------------------------------
// Main kernel: one block = (batch b, gene chunk ch).
//   Phase 0: compute pre1, mask; stash masked W1 [k][i] (swizzled) + h in smem.
//   Phase 1: V[i,g] = sum_k mW1[i,k]*W2[k,g] with packed f32x2 FMA;
//            fold in pre2[g] = sum_k h[k]*W2[k,g].
//   Epilogue: c = sigma^2 * theta / (mu*(mu+theta)+eps); U = sqrt(c)*V -> smem.
//   Phase 2: 32x32 SYRK over the 512-g tile, write partial Gram.
// ---------------------------------------------------------------------------
__global__ void __launch_bounds__(NT, 1)
pullback_main(const float* __restrict__ z,  const float* __restrict__ W1,
              const float* __restrict__ b1, const float* __restrict__ W2,
              const float* __restrict__ b2, const float* __restrict__ lth)
{
    extern __shared__ float smem[];
    float* sW1m = smem;                 // [512][32] masked W1, 16B-XOR swizzled
    float* sU   = sW1m + HID * DLAT;    // [512][32] U tile, same swizzle
    float* sH   = sU   + GT  * DLAT;    // [512] relu(pre1)
    float* sZ   = sH   + HID;           // [32]

    const int tid = threadIdx.x;
    const int b   = blockIdx.x;
    const int ch  = blockIdx.y;
    const int g0  = ch * GC;

    if (tid < DLAT) sZ[tid] = z[b * DLAT + tid];
    __syncthreads();

    // ---- Phase 0: pre1 / mask / masked W1 ----
    for (int jk = 0; jk < HID / NT; ++jk) {
        const int k = tid + jk * NT;
        float wv[DLAT];
        float pre = b1[k];
        #pragma unroll
        for (int i = 0; i < DLAT; ++i) {
            wv[i] = W1[i * HID + k];          // coalesced across tid
            pre = fmaf(sZ[i], wv[i], pre);
        }
        const bool act = pre > 0.0f;
        sH[k] = act ? pre : 0.0f;
        const int s7 = (k & 7) << 2;
        #pragma unroll
        for (int q = 0; q < 8; ++q) {
            float4 v;
            v.x = act ? wv[4*q+0] : 0.0f;
            v.y = act ? wv[4*q+1] : 0.0f;
            v.z = act ? wv[4*q+2] : 0.0f;
            v.w = act ? wv[4*q+3] : 0.0f;
            *reinterpret_cast<float4*>(sW1m + k * DLAT + (((q << 2)) ^ s7)) = v;
        }
    }
    __syncthreads();

    // ---- Phase 1 setup ----
    int  gidx[4];
    bool gval[4];
    #pragma unroll
    for (int j = 0; j < 4; ++j) {
        const int gl = j * NT + tid;
        gval[j] = (gl < GC);
        gidx[j] = g0 + (gval[j] ? gl : 0);
    }

    unsigned long long acc[4][16];
    #pragma unroll
    for (int j = 0; j < 4; ++j)
        #pragma unroll
        for (int p = 0; p < 16; ++p) acc[j][p] = 0ULL;
    float pr2[4] = {0.f, 0.f, 0.f, 0.f};

    const float* w2p0 = W2 + gidx[0];
    const float* w2p1 = W2 + gidx[1];
    const float* w2p2 = W2 + gidx[2];
    const float* w2p3 = W2 + gidx[3];

    #pragma unroll 2
    for (int k = 0; k < HID; ++k) {
        const float hk = sH[k];
        float w2v[4];
        w2v[0] = __ldg(w2p0);
        w2v[1] = __ldg(w2p1);
        w2v[2] = __ldg(w2p2);
        w2v[3] = __ldg(w2p3);
        w2p0 += GENES; w2p1 += GENES; w2p2 += GENES; w2p3 += GENES;

        unsigned long long w2pk[4];
        #pragma unroll
        for (int j = 0; j < 4; ++j) {
            const unsigned int u = __float_as_uint(w2v[j]);
            asm("mov.b64 %0, {%1,%1};" : "=l"(w2pk[j]) : "r"(u));
            pr2[j] = fmaf(hk, w2v[j], pr2[j]);
        }

        const float* rowp = sW1m + k * DLAT;
        const int s7 = (k & 7) << 2;
        #pragma unroll
        for (int q = 0; q < 8; ++q) {
            const ulonglong2 t =
                *reinterpret_cast<const ulonglong2*>(rowp + ((q << 2) ^ s7));
            #pragma unroll
            for (int j = 0; j < 4; ++j) {
                asm("fma.rn.f32x2 %0, %1, %2, %0;"
                    : "+l"(acc[j][2*q])     : "l"(t.x), "l"(w2pk[j]));
                asm("fma.rn.f32x2 %0, %1, %2, %0;"
                    : "+l"(acc[j][2*q + 1]) : "l"(t.y), "l"(w2pk[j]));
            }
        }
    }

    // ---- Epilogue: per-gene weight, write U = sqrt(c)*V ----
    #pragma unroll
    for (int j = 0; j < 4; ++j) {
        const int gl = j * NT + tid;
        float sc = 0.0f;
        if (gval[j]) {
            const int g = gidx[j];
            const float x  = pr2[j] + b2[g];
            const float mu = (x > 0.f) ? (x + log1pf(__expf(-x)))
                                       : log1pf(__expf(x));
            const float sg = 1.0f / (1.0f + __expf(-x));
            const float th = __expf(lth[g]);
            const float wt = th / fmaf(mu, mu + th, 1e-6f);
            sc = sg * sqrtf(wt);
        }
        float* urow = sU + gl * DLAT;
        const int s7 = (gl & 7) << 2;
        #pragma unroll
        for (int q = 0; q < 8; ++q) {
            unsigned int l0, h0, l1, h1;
            asm("mov.b64 {%0,%1}, %2;" : "=r"(l0), "=r"(h0) : "l"(acc[j][2*q]));
            asm("mov.b64 {%0,%1}, %2;" : "=r"(l1), "=r"(h1) : "l"(acc[j][2*q+1]));
            float4 v;
            v.x = sc * __uint_as_float(l0);
            v.y = sc * __uint_as_float(h0);
            v.z = sc * __uint_as_float(l1);
            v.w = sc * __uint_as_float(h1);
            *reinterpret_cast<float4*>(urow + ((q << 2) ^ s7)) = v;
        }
    }
    __syncthreads();

    // ---- Phase 2: Gram partial = U U^T (register-tiled 4x2 per thread) ----
    const int ti = tid & 7;         // i-block of 4 -> i0 = 4*ti
    const int tj = tid >> 3;        // j-block of 2 -> j0 = 2*tj
    const int jq = tj >> 1;         // 16B unit holding j0
    const int jo = (tj & 1) << 1;   // float offset inside unit
    float ga[4][2] = {{0.f,0.f},{0.f,0.f},{0.f,0.f},{0.f,0.f}};

    #pragma unroll 4
    for (int gl = 0; gl < GT; ++gl) {
        const float* row = sU + gl * DLAT;
        const int s7 = (gl & 7);
        const float4 av =
            *reinterpret_cast<const float4*>(row + (((ti ^ s7)) << 2));
        const float* bp = row + ((jq ^ s7) << 2) + jo;
        const float b0v = bp[0];
        const float b1v = bp[1];
        ga[0][0] = fmaf(av.x, b0v, ga[0][0]); ga[0][1] = fmaf(av.x, b1v, ga[0][1]);
        ga[1][0] = fmaf(av.y, b0v, ga[1][0]); ga[1][1] = fmaf(av.y, b1v, ga[1][1]);
        ga[2][0] = fmaf(av.z, b0v, ga[2][0]); ga[2][1] = fmaf(av.z, b1v, ga[2][1]);
        ga[3][0] = fmaf(av.w, b0v, ga[3][0]); ga[3][1] = fmaf(av.w, b1v, ga[3][1]);
    }

    float* dst = g_gramPart + ((size_t)ch * BATCH + b) * (DLAT * DLAT);
    #pragma unroll
    for (int ii = 0; ii < 4; ++ii)
        #pragma unroll
        for (int jj = 0; jj < 2; ++jj)
            dst[(4 * ti + ii) * DLAT + (2 * tj + jj)] = ga[ii][jj];
}

// ---------------------------------------------------------------------------
// Per-batch loss: sum_ij (sum_ch Gram_partial - I)^2  (deterministic)
// ---------------------------------------------------------------------------
__global__ void __launch_bounds__(256)
loss_per_b_kernel()
{
    const int b = blockIdx.x;
    const int t = threadIdx.x;
    float accl = 0.0f;
    #pragma unroll
    for (int r = 0; r < 4; ++r) {
        const int ij = t + r * 256;
        float s = 0.0f;
        #pragma unroll
        for (int c = 0; c < NCH; ++c)
            s += g_gramPart[((size_t)c * BATCH + b) * 1024 + ij];
        if (ij % 33 == 0) s -= 1.0f;   // ALPHA * I on the diagonal
        accl = fmaf(s, s, accl);
    }
    __shared__ float red[256];
    red[t] = accl;
    __syncthreads();
    for (int o = 128; o > 0; o >>= 1) {
        if (t < o) red[t] += red[t + o];
        __syncthreads();
    }
    if (t == 0) g_lossb[b] = red[0];
}

__global__ void __launch_bounds__(256)
final_reduce_kernel(float* __restrict__ out)
{
    const int t = threadIdx.x;
    __shared__ float red[256];
    red[t] = g_lossb[t];
    __syncthreads();
    for (int o = 128; o > 0; o >>= 1) {
        if (t < o) red[t] += red[t + o];
        __syncthreads();
    }
    if (t == 0) out[0] = red[0] * (1.0f / (float)BATCH);
}

// ---------------------------------------------------------------------------
extern "C" void kernel_launch(void* const* d_in, const int* in_sizes, int n_in,
                              void* d_out, int out_size)
{
    const float* z   = (const float*)d_in[0];
    const float* W1  = (const float*)d_in[1];
    const float* b1  = (const float*)d_in[2];
    const float* W2  = (const float*)d_in[3];
    const float* b2  = (const float*)d_in[4];
    const float* lth = (const float*)d_in[5];

    const size_t smem_bytes =
        (size_t)(HID * DLAT + GT * DLAT + HID + DLAT) * sizeof(float); // 133,248 B
    cudaFuncSetAttribute(pullback_main,
                         cudaFuncAttributeMaxDynamicSharedMemorySize,
                         (int)smem_bytes);

    dim3 grid(BATCH, NCH);
    pullback_main<<<grid, NT, smem_bytes>>>(z, W1, b1, W2, b2, lth);
    loss_per_b_kernel<<<BATCH, 256>>>();
    final_reduce_kernel<<<1, 256>>>((float*)d_out);
}

// round 2
// speedup vs baseline: 1.4598x; 1.4598x over previous
#include <cuda_runtime.h>
#include <cstdint>

#define BATCH 256
#define DLAT  32
#define HID   512
#define GENES 4000
#define NCH   8
#define GC    500      // genes per chunk (8*500 = 4000)
#define GT    512      // g slots per block (2 per thread * 256 threads)
#define NT    256

// Deterministic partial-Gram buffer: [chunk][batch][32*32]
__device__ float g_gramPart[(size_t)NCH * BATCH * DLAT * DLAT];
__device__ float g_lossb[BATCH];

// ---------------------------------------------------------------------------
// Main kernel: one block = (batch b, gene chunk ch).
//   Phase 0: compute pre1, mask; stash masked W1 [k][i] (swizzled) + h in smem.
//   Phase 1: V[i,g] = sum_k mW1[i,k]*W2[k,g] with packed f32x2 FMA;
//            fold in pre2[g] = sum_k h[k]*W2[k,g].
//   Epilogue: c = sigma^2 * theta / (mu*(mu+theta)+eps); U = sqrt(c)*V,
//             written back OVER the masked-W1 buffer (phase 1 is done with it).
//   Phase 2: 32x32 SYRK over the 512-g tile, write partial Gram.
// ---------------------------------------------------------------------------
__global__ void __launch_bounds__(NT, 2)
pullback_main(const float* __restrict__ z,  const float* __restrict__ W1,
              const float* __restrict__ b1, const float* __restrict__ W2,
              const float* __restrict__ b2, const float* __restrict__ lth)
{
    extern __shared__ float smem[];
    float* sW1m = smem;                 // [512][32] masked W1, 16B-XOR swizzled
    float* sU   = smem;                 // [512][32] U tile (REUSES sW1m)
    float* sH   = sW1m + HID * DLAT;    // [512] relu(pre1)
    float* sZ   = sH   + HID;           // [32]

    const int tid = threadIdx.x;
    const int b   = blockIdx.x;
    const int ch  = blockIdx.y;
    const int g0  = ch * GC;

    if (tid < DLAT) sZ[tid] = z[b * DLAT + tid];
    __syncthreads();

    // ---- Phase 0: pre1 / mask / masked W1 ----
    for (int jk = 0; jk < HID / NT; ++jk) {
        const int k = tid + jk * NT;
        float wv[DLAT];
        float pre = b1[k];
        #pragma unroll
        for (int i = 0; i < DLAT; ++i) {
            wv[i] = W1[i * HID + k];          // coalesced across tid
            pre = fmaf(sZ[i], wv[i], pre);
        }
        const bool act = pre > 0.0f;
        sH[k] = act ? pre : 0.0f;
        const int s7 = (k & 7) << 2;
        #pragma unroll
        for (int q = 0; q < 8; ++q) {
            float4 v;
            v.x = act ? wv[4*q+0] : 0.0f;
            v.y = act ? wv[4*q+1] : 0.0f;
            v.z = act ? wv[4*q+2] : 0.0f;
            v.w = act ? wv[4*q+3] : 0.0f;
            *reinterpret_cast<float4*>(sW1m + k * DLAT + (((q << 2)) ^ s7)) = v;
        }
    }
    __syncthreads();

    // ---- Phase 1 setup: 2 genes per thread ----
    int  gidx[2];
    bool gval[2];
    #pragma unroll
    for (int j = 0; j < 2; ++j) {
        const int gl = j * NT + tid;
        gval[j] = (gl < GC);
        gidx[j] = g0 + (gval[j] ? gl : 0);
    }

    unsigned long long acc[2][16];
    #pragma unroll
    for (int j = 0; j < 2; ++j)
        #pragma unroll
        for (int p = 0; p < 16; ++p) acc[j][p] = 0ULL;
    float pr2[2] = {0.f, 0.f};

    const float* w2p0 = W2 + gidx[0];
    const float* w2p1 = W2 + gidx[1];

    #pragma unroll 2
    for (int k = 0; k < HID; ++k) {
        const float hk = sH[k];
        float w2v[2];
        w2v[0] = __ldg(w2p0);
        w2v[1] = __ldg(w2p1);
        w2p0 += GENES; w2p1 += GENES;

        unsigned long long w2pk[2];
        #pragma unroll
        for (int j = 0; j < 2; ++j) {
            const unsigned int u = __float_as_uint(w2v[j]);
            asm("mov.b64 %0, {%1,%1};" : "=l"(w2pk[j]) : "r"(u));
            pr2[j] = fmaf(hk, w2v[j], pr2[j]);
        }

        const float* rowp = sW1m + k * DLAT;
        const int s7 = (k & 7) << 2;
        #pragma unroll
        for (int q = 0; q < 8; ++q) {
            const ulonglong2 t =
                *reinterpret_cast<const ulonglong2*>(rowp + ((q << 2) ^ s7));
            #pragma unroll
            for (int j = 0; j < 2; ++j) {
                asm("fma.rn.f32x2 %0, %1, %2, %0;"
                    : "+l"(acc[j][2*q])     : "l"(t.x), "l"(w2pk[j]));
                asm("fma.rn.f32x2 %0, %1, %2, %0;"
                    : "+l"(acc[j][2*q + 1]) : "l"(t.y), "l"(w2pk[j]));
            }
        }
    }

    // All warps must finish READING sW1m before we overwrite it with U.
    __syncthreads();

    // ---- Epilogue: per-gene weight, write U = sqrt(c)*V over sW1m ----
    #pragma unroll
    for (int j = 0; j < 2; ++j) {
        const int gl = j * NT + tid;
        float sc = 0.0f;
        if (gval[j]) {
            const int g = gidx[j];
            const float x  = pr2[j] + b2[g];
            const float mu = (x > 0.f) ? (x + log1pf(__expf(-x)))
                                       : log1pf(__expf(x));
            const float sg = 1.0f / (1.0f + __expf(-x));
            const float th = __expf(lth[g]);
            const float wt = th / fmaf(mu, mu + th, 1e-6f);
            sc = sg * sqrtf(wt);
        }
        float* urow = sU + gl * DLAT;
        const int s7 = (gl & 7) << 2;
        #pragma unroll
        for (int q = 0; q < 8; ++q) {
            unsigned int l0, h0, l1, h1;
            asm("mov.b64 {%0,%1}, %2;" : "=r"(l0), "=r"(h0) : "l"(acc[j][2*q]));
            asm("mov.b64 {%0,%1}, %2;" : "=r"(l1), "=r"(h1) : "l"(acc[j][2*q+1]));
            float4 v;
            v.x = sc * __uint_as_float(l0);
            v.y = sc * __uint_as_float(h0);
            v.z = sc * __uint_as_float(l1);
            v.w = sc * __uint_as_float(h1);
            *reinterpret_cast<float4*>(urow + ((q << 2) ^ s7)) = v;
        }
    }
    __syncthreads();

    // ---- Phase 2: Gram partial = U U^T (2x2 tile per thread, 16x16 grid) ----
    const int ti = tid & 15;        // i0 = 2*ti
    const int tj = tid >> 4;        // j0 = 2*tj
    const int iu = ti >> 1, io = (ti & 1) << 1;
    const int ju = tj >> 1, jo = (tj & 1) << 1;
    float ga[2][2] = {{0.f, 0.f}, {0.f, 0.f}};

    #pragma unroll 4
    for (int gl = 0; gl < GT; ++gl) {
        const float* row = sU + gl * DLAT;
        const int s7 = (gl & 7);
        const float2 av = *reinterpret_cast<const float2*>(row + ((iu ^ s7) << 2) + io);
        const float2 bv = *reinterpret_cast<const float2*>(row + ((ju ^ s7) << 2) + jo);
        ga[0][0] = fmaf(av.x, bv.x, ga[0][0]);
        ga[0][1] = fmaf(av.x, bv.y, ga[0][1]);
        ga[1][0] = fmaf(av.y, bv.x, ga[1][0]);
        ga[1][1] = fmaf(av.y, bv.y, ga[1][1]);
    }

    float* dst = g_gramPart + ((size_t)ch * BATCH + b) * (DLAT * DLAT);
    #pragma unroll
    for (int ii = 0; ii < 2; ++ii)
        #pragma unroll
        for (int jj = 0; jj < 2; ++jj)
            dst[(2 * ti + ii) * DLAT + (2 * tj + jj)] = ga[ii][jj];
}

// ---------------------------------------------------------------------------
// Per-batch loss: sum_ij (sum_ch Gram_partial - I)^2  (deterministic)
// ---------------------------------------------------------------------------
__global__ void __launch_bounds__(256)
loss_per_b_kernel()
{
    const int b = blockIdx.x;
    const int t = threadIdx.x;
    float accl = 0.0f;
    #pragma unroll
    for (int r = 0; r < 4; ++r) {
        const int ij = t + r * 256;
        float s = 0.0f;
        #pragma unroll
        for (int c = 0; c < NCH; ++c)
            s += g_gramPart[((size_t)c * BATCH + b) * 1024 + ij];
        if (ij % 33 == 0) s -= 1.0f;   // ALPHA * I on the diagonal
        accl = fmaf(s, s, accl);
    }
    __shared__ float red[256];
    red[t] = accl;
    __syncthreads();
    for (int o = 128; o > 0; o >>= 1) {
        if (t < o) red[t] += red[t + o];
        __syncthreads();
    }
    if (t == 0) g_lossb[b] = red[0];
}

__global__ void __launch_bounds__(256)
final_reduce_kernel(float* __restrict__ out)
{
    const int t = threadIdx.x;
    __shared__ float red[256];
    red[t] = g_lossb[t];
    __syncthreads();
    for (int o = 128; o > 0; o >>= 1) {
        if (t < o) red[t] += red[t + o];
        __syncthreads();
    }
    if (t == 0) out[0] = red[0] * (1.0f / (float)BATCH);
}

// ---------------------------------------------------------------------------
extern "C" void kernel_launch(void* const* d_in, const int* in_sizes, int n_in,
                              void* d_out, int out_size)
{
    const float* z   = (const float*)d_in[0];
    const float* W1  = (const float*)d_in[1];
    const float* b1  = (const float*)d_in[2];
    const float* W2  = (const float*)d_in[3];
    const float* b2  = (const float*)d_in[4];
    const float* lth = (const float*)d_in[5];

    const size_t smem_bytes =
        (size_t)(HID * DLAT + HID + DLAT) * sizeof(float);  // 67,712 B
    cudaFuncSetAttribute(pullback_main,
                         cudaFuncAttributeMaxDynamicSharedMemorySize,
                         (int)smem_bytes);

    dim3 grid(BATCH, NCH);
    pullback_main<<<grid, NT, smem_bytes>>>(z, W1, b1, W2, b2, lth);
    loss_per_b_kernel<<<BATCH, 256>>>();
    final_reduce_kernel<<<1, 256>>>((float*)d_out);
}

// round 3
// speedup vs baseline: 1.9102x; 1.3085x over previous
#include <cuda_runtime.h>
#include <cstdint>

#define BATCH 256
#define DLAT  32
#define HID   512
#define GENES 4000
#define NCH   8
#define GC    500      // genes per chunk; 500 = 2*250 -> tid<250 owns 2 genes
#define GT    512      // U rows per block (rows 500..511 written as zeros)
#define NT    256

// Deterministic partial-Gram buffer: [chunk][batch][32*32]
__device__ float g_gramPart[(size_t)NCH * BATCH * DLAT * DLAT];
__device__ float g_lossb[BATCH];

#define FMA2(accv, av, bv) \
    asm("fma.rn.f32x2 %0, %1, %2, %0;" : "+l"(accv) : "l"(av), "l"(bv))

// ---------------------------------------------------------------------------
// Main kernel: one block = (batch b, gene chunk ch).
//   Phase 0: pre1/mask; masked W1 [k][i] into smem, 16B-XOR swizzled
//            (swizzle exists ONLY so phase-0 STS.128 is conflict-free).
//   Phase 1: V[i,g] for 2 consecutive genes/thread; k-loop unrolled x8 so all
//            LDS/LDG offsets are compile-time immediates (no address ALU).
//   Epilogue: U = sqrt(c)*V written UNSWIZZLED over the same buffer.
//   Phase 2: 32x32 SYRK with f32x2, per-thread-constant addresses.
// ---------------------------------------------------------------------------
__global__ void __launch_bounds__(NT, 2)
pullback_main(const float* __restrict__ z,  const float* __restrict__ W1,
              const float* __restrict__ b1, const float* __restrict__ W2,
              const float* __restrict__ b2, const float* __restrict__ lth)
{
    extern __shared__ float smem[];
    float* sW1m = smem;                 // [512][32] masked W1 (swizzled)
    float* sU   = smem;                 // [512][32] U tile (UNSWIZZLED, reuse)
    float* sH   = sW1m + HID * DLAT;    // [512] relu(pre1)
    float* sZ   = sH   + HID;           // [32]

    const int tid = threadIdx.x;
    const int b   = blockIdx.x;
    const int ch  = blockIdx.y;
    const int g0  = ch * GC;

    if (tid < DLAT) sZ[tid] = z[b * DLAT + tid];
    __syncthreads();

    // ---- Phase 0: pre1 / mask / masked W1 (swizzled, conflict-free STS) ----
    for (int jk = 0; jk < HID / NT; ++jk) {
        const int k = tid + jk * NT;
        float wv[DLAT];
        float pre = b1[k];
        #pragma unroll
        for (int i = 0; i < DLAT; ++i) {
            wv[i] = W1[i * HID + k];          // coalesced across tid
            pre = fmaf(sZ[i], wv[i], pre);
        }
        const bool act = pre > 0.0f;
        sH[k] = act ? pre : 0.0f;
        const int s7 = (k & 7) << 2;
        #pragma unroll
        for (int q = 0; q < 8; ++q) {
            float4 v;
            v.x = act ? wv[4*q+0] : 0.0f;
            v.y = act ? wv[4*q+1] : 0.0f;
            v.z = act ? wv[4*q+2] : 0.0f;
            v.w = act ? wv[4*q+3] : 0.0f;
            *reinterpret_cast<float4*>(sW1m + k * DLAT + ((q << 2) ^ s7)) = v;
        }
    }
    __syncthreads();

    // ---- Phase 1: 2 consecutive genes per thread ----
    const bool gv  = (tid < GC / 2);               // 250 active threads
    const int  gp  = g0 + (gv ? 2 * tid : 0);      // clamped for inert threads

    unsigned long long acc0[16], acc1[16];
    #pragma unroll
    for (int p = 0; p < 16; ++p) { acc0[p] = 0ULL; acc1[p] = 0ULL; }
    float pr2a = 0.0f, pr2b = 0.0f;

    const float* w2k  = W2 + gp;
    const float* rowp = sW1m;
    const float* sHp  = sH;

    #pragma unroll 1
    for (int k8 = 0; k8 < HID / 8; ++k8) {
        #pragma unroll
        for (int kk = 0; kk < 8; ++kk) {
            const float  hk  = sHp[kk];
            const float2 w2v =
                *reinterpret_cast<const float2*>(w2k + kk * GENES); // LDG.64
            unsigned long long a0, a1;
            asm("mov.b64 %0, {%1,%1};" : "=l"(a0) : "r"(__float_as_uint(w2v.x)));
            asm("mov.b64 %0, {%1,%1};" : "=l"(a1) : "r"(__float_as_uint(w2v.y)));
            pr2a = fmaf(hk, w2v.x, pr2a);
            pr2b = fmaf(hk, w2v.y, pr2b);

            const float* rp = rowp + kk * DLAT;
            #pragma unroll
            for (int q = 0; q < 8; ++q) {
                // offset compile-time: (4q)^(4kk)
                const ulonglong2 t = *reinterpret_cast<const ulonglong2*>(
                    rp + (((q << 2)) ^ ((kk << 2))));
                FMA2(acc0[2*q],   t.x, a0);
                FMA2(acc0[2*q+1], t.y, a0);
                FMA2(acc1[2*q],   t.x, a1);
                FMA2(acc1[2*q+1], t.y, a1);
            }
        }
        rowp += 8 * DLAT;
        w2k  += 8 * GENES;
        sHp  += 8;
    }

    // All warps must finish READING sW1m before overwriting with U.
    __syncthreads();

    // ---- Epilogue: per-gene weight, U = sqrt(c)*V, UNSWIZZLED rows ----
    #pragma unroll
    for (int j = 0; j < 2; ++j) {
        const int gl = 2 * tid + j;            // row in sU
        float sc = 0.0f;
        if (gv) {
            const int g = gp + j;
            const float x  = (j == 0 ? pr2a : pr2b) + b2[g];
            const float mu = (x > 0.f) ? (x + log1pf(__expf(-x)))
                                       : log1pf(__expf(x));
            const float sg = 1.0f / (1.0f + __expf(-x));
            const float th = __expf(lth[g]);
            const float wt = th / fmaf(mu, mu + th, 1e-6f);
            sc = sg * sqrtf(wt);
        }
        const unsigned long long* accp = (j == 0) ? acc0 : acc1;
        float* urow = sU + gl * DLAT;
        #pragma unroll
        for (int q = 0; q < 8; ++q) {
            unsigned int l0, h0, l1, h1;
            asm("mov.b64 {%0,%1}, %2;" : "=r"(l0), "=r"(h0) : "l"(accp[2*q]));
            asm("mov.b64 {%0,%1}, %2;" : "=r"(l1), "=r"(h1) : "l"(accp[2*q+1]));
            float4 v;
            v.x = sc * __uint_as_float(l0);
            v.y = sc * __uint_as_float(h0);
            v.z = sc * __uint_as_float(l1);
            v.w = sc * __uint_as_float(h1);
            *reinterpret_cast<float4*>(urow + (q << 2)) = v;
        }
    }
    __syncthreads();

    // ---- Phase 2: Gram partial = U U^T, f32x2, 2x2 tile per thread ----
    const int ti = tid & 15;        // i0 = 2*ti
    const int tj = tid >> 4;        // j0 = 2*tj
    const float* pa = sU + 2 * ti;
    const float* pb = sU + 2 * tj;
    unsigned long long ga0 = 0ULL, ga1 = 0ULL;  // rows i0, i0+1 x cols {j0,j0+1}

    #pragma unroll 1
    for (int g8 = 0; g8 < GT / 8; ++g8) {
        #pragma unroll
        for (int s = 0; s < 8; ++s) {
            const unsigned long long avu =
                *reinterpret_cast<const unsigned long long*>(pa + s * DLAT);
            const unsigned long long bvu =
                *reinterpret_cast<const unsigned long long*>(pb + s * DLAT);
            unsigned int alo, ahi;
            asm("mov.b64 {%0,%1}, %2;" : "=r"(alo), "=r"(ahi) : "l"(avu));
            unsigned long long ad0, ad1;
            asm("mov.b64 %0, {%1,%1};" : "=l"(ad0) : "r"(alo));
            asm("mov.b64 %0, {%1,%1};" : "=l"(ad1) : "r"(ahi));
            FMA2(ga0, ad0, bvu);
            FMA2(ga1, ad1, bvu);
        }
        pa += 8 * DLAT;
        pb += 8 * DLAT;
    }

    float* dst = g_gramPart + ((size_t)ch * BATCH + b) * (DLAT * DLAT);
    {
        unsigned int l0, h0, l1, h1;
        asm("mov.b64 {%0,%1}, %2;" : "=r"(l0), "=r"(h0) : "l"(ga0));
        asm("mov.b64 {%0,%1}, %2;" : "=r"(l1), "=r"(h1) : "l"(ga1));
        dst[(2*ti    ) * DLAT + 2*tj    ] = __uint_as_float(l0);
        dst[(2*ti    ) * DLAT + 2*tj + 1] = __uint_as_float(h0);
        dst[(2*ti + 1) * DLAT + 2*tj    ] = __uint_as_float(l1);
        dst[(2*ti + 1) * DLAT + 2*tj + 1] = __uint_as_float(h1);
    }
}

// ---------------------------------------------------------------------------
// Per-batch loss: sum_ij (sum_ch Gram_partial - I)^2  (deterministic)
// ---------------------------------------------------------------------------
__global__ void __launch_bounds__(256)
loss_per_b_kernel()
{
    const int b = blockIdx.x;
    const int t = threadIdx.x;
    float accl = 0.0f;
    #pragma unroll
    for (int r = 0; r < 4; ++r) {
        const int ij = t + r * 256;
        float s = 0.0f;
        #pragma unroll
        for (int c = 0; c < NCH; ++c)
            s += g_gramPart[((size_t)c * BATCH + b) * 1024 + ij];
        if (ij % 33 == 0) s -= 1.0f;   // ALPHA * I on the diagonal
        accl = fmaf(s, s, accl);
    }
    __shared__ float red[256];
    red[t] = accl;
    __syncthreads();
    for (int o = 128; o > 0; o >>= 1) {
        if (t < o) red[t] += red[t + o];
        __syncthreads();
    }
    if (t == 0) g_lossb[b] = red[0];
}

__global__ void __launch_bounds__(256)
final_reduce_kernel(float* __restrict__ out)
{
    const int t = threadIdx.x;
    __shared__ float red[256];
    red[t] = g_lossb[t];
    __syncthreads();
    for (int o = 128; o > 0; o >>= 1) {
        if (t < o) red[t] += red[t + o];
        __syncthreads();
    }
    if (t == 0) out[0] = red[0] * (1.0f / (float)BATCH);
}

// ---------------------------------------------------------------------------
extern "C" void kernel_launch(void* const* d_in, const int* in_sizes, int n_in,
                              void* d_out, int out_size)
{
    const float* z   = (const float*)d_in[0];
    const float* W1  = (const float*)d_in[1];
    const float* b1  = (const float*)d_in[2];
    const float* W2  = (const float*)d_in[3];
    const float* b2  = (const float*)d_in[4];
    const float* lth = (const float*)d_in[5];

    const size_t smem_bytes =
        (size_t)(HID * DLAT + HID + DLAT) * sizeof(float);  // 67,712 B
    cudaFuncSetAttribute(pullback_main,
                         cudaFuncAttributeMaxDynamicSharedMemorySize,
                         (int)smem_bytes);

    dim3 grid(BATCH, NCH);
    pullback_main<<<grid, NT, smem_bytes>>>(z, W1, b1, W2, b2, lth);
    loss_per_b_kernel<<<BATCH, 256>>>();
    final_reduce_kernel<<<1, 256>>>((float*)d_out);
}

// round 4
// speedup vs baseline: 1.9555x; 1.0238x over previous
#include <cuda_runtime.h>
#include <cstdint>

#define BATCH 256
#define DLAT  32
#define HID   512
#define GENES 4000
#define NCH   8
#define GC    500      // genes per chunk; 500 = 4*125 -> tg<125 owns 4 genes
#define GT    512      // U rows per block (rows 500..511 written as zeros)
#define NT    256
#define PANEL 2052     // floats per A-panel: 512*4 + 4 skew (8208 B, 16B-aligned)

// Deterministic partial-Gram buffer: [chunk][batch][32*32]
__device__ float g_gramPart[(size_t)NCH * BATCH * DLAT * DLAT];
__device__ float g_lossb[BATCH];

#define FMA2(accv, av, bv) \
    asm("fma.rn.f32x2 %0, %1, %2, %0;" : "+l"(accv) : "l"(av), "l"(bv))
#define SPLAT2(dst, s) \
    asm("mov.b64 %0, {%1,%1};" : "=l"(dst) : "r"(__float_as_uint(s)))
#define PACK2(dst, lo, hi) \
    asm("mov.b64 %0, {%1,%2};" : "=l"(dst) : "r"(__float_as_uint(lo)), "r"(__float_as_uint(hi)))

// ---------------------------------------------------------------------------
// Main kernel: one block = (batch b, gene chunk ch).
//   Phase 0: pre1/mask; masked W1 stored as 8 skewed PANELS [k][4 floats]
//            (conflict-free STS, immediate-offset broadcast LDS in phase 1).
//   Phase 1: thread (th = i-half, tg = 4 consecutive genes) computes
//            V[16 i x 4 g] with f32x2 FMA; pre2 folded in as packed FFMA2.
//   Epilogue: U = sqrt(c)*V written row-major [512][32] over the same buffer.
//   Phase 2: 32x32 SYRK with f32x2 (as R3).
// ---------------------------------------------------------------------------
__global__ void __launch_bounds__(NT, 2)
pullback_main(const float* __restrict__ z,  const float* __restrict__ W1,
              const float* __restrict__ b1, const float* __restrict__ W2,
              const float* __restrict__ b2, const float* __restrict__ lth)
{
    extern __shared__ float smem[];
    float* sW1m = smem;                  // 8 panels * PANEL floats
    float* sU   = smem;                  // [512][32] U tile (reuse)
    float* sH   = smem + 8 * PANEL;      // [512] relu(pre1)
    float* sZ   = sH + HID;              // [32]

    const int tid = threadIdx.x;
    const int b   = blockIdx.x;
    const int ch  = blockIdx.y;
    const int g0  = ch * GC;

    if (tid < DLAT) sZ[tid] = z[b * DLAT + tid];
    __syncthreads();

    // ---- Phase 0: pre1 / mask / masked W1 into panels ----
    for (int jk = 0; jk < HID / NT; ++jk) {
        const int k = tid + jk * NT;
        float wv[DLAT];
        float pre = b1[k];
        #pragma unroll
        for (int i = 0; i < DLAT; ++i) {
            wv[i] = W1[i * HID + k];          // coalesced across tid
            pre = fmaf(sZ[i], wv[i], pre);
        }
        const bool act = pre > 0.0f;
        sH[k] = act ? pre : 0.0f;
        #pragma unroll
        for (int q = 0; q < 8; ++q) {
            float4 v;
            v.x = act ? wv[4*q+0] : 0.0f;
            v.y = act ? wv[4*q+1] : 0.0f;
            v.z = act ? wv[4*q+2] : 0.0f;
            v.w = act ? wv[4*q+3] : 0.0f;
            *reinterpret_cast<float4*>(sW1m + q * PANEL + k * 4) = v;
        }
    }
    __syncthreads();

    // ---- Phase 1: 16 i (one half) x 4 consecutive genes per thread ----
    const int  th = tid & 1;               // i-half: cols th*16 .. th*16+15
    const int  tg = tid >> 1;              // gene group
    const bool gv = (tg < GC / 4);         // 125 active groups
    const int  gp = g0 + (gv ? 4 * tg : 0);

    // acc[j*8 + e]: gene j (0..3), i-pair e (0..7) within this thread's half
    unsigned long long acc[32];
    #pragma unroll
    for (int p = 0; p < 32; ++p) acc[p] = 0ULL;
    unsigned long long pr01 = 0ULL, pr23 = 0ULL;   // packed pre2 accumulators

    const float* rowp = sW1m + th * (4 * PANEL);
    const float* sHp  = sH;
    const float* w2k  = W2 + gp;

    #pragma unroll 1
    for (int k8 = 0; k8 < HID / 8; ++k8) {
        #pragma unroll
        for (int kk = 0; kk < 8; ++kk) {
            const float4 w2v =
                *reinterpret_cast<const float4*>(w2k + kk * GENES); // LDG.128
            const float hk = sHp[kk];

            unsigned long long a0, a1, a2, a3, hkp, w01, w23;
            SPLAT2(a0, w2v.x);
            SPLAT2(a1, w2v.y);
            SPLAT2(a2, w2v.z);
            SPLAT2(a3, w2v.w);
            SPLAT2(hkp, hk);
            PACK2(w01, w2v.x, w2v.y);
            PACK2(w23, w2v.z, w2v.w);
            FMA2(pr01, hkp, w01);
            FMA2(pr23, hkp, w23);

            #pragma unroll
            for (int q = 0; q < 4; ++q) {
                const ulonglong2 t = *reinterpret_cast<const ulonglong2*>(
                    rowp + q * PANEL + kk * 4);     // immediate offsets
                FMA2(acc[0*8 + 2*q],     t.x, a0);
                FMA2(acc[0*8 + 2*q + 1], t.y, a0);
                FMA2(acc[1*8 + 2*q],     t.x, a1);
                FMA2(acc[1*8 + 2*q + 1], t.y, a1);
                FMA2(acc[2*8 + 2*q],     t.x, a2);
                FMA2(acc[2*8 + 2*q + 1], t.y, a2);
                FMA2(acc[3*8 + 2*q],     t.x, a3);
                FMA2(acc[3*8 + 2*q + 1], t.y, a3);
            }
        }
        rowp += 32;          // 8 k * 4 floats
        w2k  += 8 * GENES;
        sHp  += 8;
    }

    // All warps must finish READING the panels before overwriting with U.
    __syncthreads();

    // ---- Epilogue: per-gene weight, U = sqrt(c)*V, row-major [512][32] ----
    float pr2f[4];
    {
        unsigned int l, h;
        asm("mov.b64 {%0,%1}, %2;" : "=r"(l), "=r"(h) : "l"(pr01));
        pr2f[0] = __uint_as_float(l); pr2f[1] = __uint_as_float(h);
        asm("mov.b64 {%0,%1}, %2;" : "=r"(l), "=r"(h) : "l"(pr23));
        pr2f[2] = __uint_as_float(l); pr2f[3] = __uint_as_float(h);
    }
    #pragma unroll
    for (int j = 0; j < 4; ++j) {
        const int row = 4 * tg + j;            // rows 500..511 get sc=0 zeros
        float sc = 0.0f;
        if (gv) {
            const int g = gp + j;
            const float x  = pr2f[j] + b2[g];
            const float mu = (x > 0.f) ? (x + log1pf(__expf(-x)))
                                       : log1pf(__expf(x));
            const float sg = 1.0f / (1.0f + __expf(-x));
            const float thv = __expf(lth[g]);
            const float wt = thv / fmaf(mu, mu + thv, 1e-6f);
            sc = sg * sqrtf(wt);
        }
        float* urow = sU + row * DLAT + th * 16;
        #pragma unroll
        for (int q = 0; q < 4; ++q) {
            unsigned int l0, h0, l1, h1;
            asm("mov.b64 {%0,%1}, %2;" : "=r"(l0), "=r"(h0) : "l"(acc[j*8 + 2*q]));
            asm("mov.b64 {%0,%1}, %2;" : "=r"(l1), "=r"(h1) : "l"(acc[j*8 + 2*q + 1]));
            float4 v;
            v.x = sc * __uint_as_float(l0);
            v.y = sc * __uint_as_float(h0);
            v.z = sc * __uint_as_float(l1);
            v.w = sc * __uint_as_float(h1);
            *reinterpret_cast<float4*>(urow + (q << 2)) = v;
        }
    }
    __syncthreads();

    // ---- Phase 2: Gram partial = U U^T, f32x2, 2x2 tile per thread ----
    const int ti = tid & 15;        // i0 = 2*ti
    const int tj = tid >> 4;        // j0 = 2*tj
    const float* pa = sU + 2 * ti;
    const float* pb = sU + 2 * tj;
    unsigned long long ga0 = 0ULL, ga1 = 0ULL;  // rows i0, i0+1 x cols {j0,j0+1}

    #pragma unroll 1
    for (int g8 = 0; g8 < GT / 8; ++g8) {
        #pragma unroll
        for (int s = 0; s < 8; ++s) {
            const unsigned long long avu =
                *reinterpret_cast<const unsigned long long*>(pa + s * DLAT);
            const unsigned long long bvu =
                *reinterpret_cast<const unsigned long long*>(pb + s * DLAT);
            unsigned int alo, ahi;
            asm("mov.b64 {%0,%1}, %2;" : "=r"(alo), "=r"(ahi) : "l"(avu));
            unsigned long long ad0, ad1;
            asm("mov.b64 %0, {%1,%1};" : "=l"(ad0) : "r"(alo));
            asm("mov.b64 %0, {%1,%1};" : "=l"(ad1) : "r"(ahi));
            FMA2(ga0, ad0, bvu);
            FMA2(ga1, ad1, bvu);
        }
        pa += 8 * DLAT;
        pb += 8 * DLAT;
    }

    float* dst = g_gramPart + ((size_t)ch * BATCH + b) * (DLAT * DLAT);
    {
        unsigned int l0, h0, l1, h1;
        asm("mov.b64 {%0,%1}, %2;" : "=r"(l0), "=r"(h0) : "l"(ga0));
        asm("mov.b64 {%0,%1}, %2;" : "=r"(l1), "=r"(h1) : "l"(ga1));
        dst[(2*ti    ) * DLAT + 2*tj    ] = __uint_as_float(l0);
        dst[(2*ti    ) * DLAT + 2*tj + 1] = __uint_as_float(h0);
        dst[(2*ti + 1) * DLAT + 2*tj    ] = __uint_as_float(l1);
        dst[(2*ti + 1) * DLAT + 2*tj + 1] = __uint_as_float(h1);
    }
}

// ---------------------------------------------------------------------------
// Per-batch loss: sum_ij (sum_ch Gram_partial - I)^2  (deterministic)
// ---------------------------------------------------------------------------
__global__ void __launch_bounds__(256)
loss_per_b_kernel()
{
    const int b = blockIdx.x;
    const int t = threadIdx.x;
    float accl = 0.0f;
    #pragma unroll
    for (int r = 0; r < 4; ++r) {
        const int ij = t + r * 256;
        float s = 0.0f;
        #pragma unroll
        for (int c = 0; c < NCH; ++c)
            s += g_gramPart[((size_t)c * BATCH + b) * 1024 + ij];
        if (ij % 33 == 0) s -= 1.0f;   // ALPHA * I on the diagonal
        accl = fmaf(s, s, accl);
    }
    __shared__ float red[256];
    red[t] = accl;
    __syncthreads();
    for (int o = 128; o > 0; o >>= 1) {
        if (t < o) red[t] += red[t + o];
        __syncthreads();
    }
    if (t == 0) g_lossb[b] = red[0];
}

__global__ void __launch_bounds__(256)
final_reduce_kernel(float* __restrict__ out)
{
    const int t = threadIdx.x;
    __shared__ float red[256];
    red[t] = g_lossb[t];
    __syncthreads();
    for (int o = 128; o > 0; o >>= 1) {
        if (t < o) red[t] += red[t + o];
        __syncthreads();
    }
    if (t == 0) out[0] = red[0] * (1.0f / (float)BATCH);
}

// ---------------------------------------------------------------------------
extern "C" void kernel_launch(void* const* d_in, const int* in_sizes, int n_in,
                              void* d_out, int out_size)
{
    const float* z   = (const float*)d_in[0];
    const float* W1  = (const float*)d_in[1];
    const float* b1  = (const float*)d_in[2];
    const float* W2  = (const float*)d_in[3];
    const float* b2  = (const float*)d_in[4];
    const float* lth = (const float*)d_in[5];

    const size_t smem_bytes =
        (size_t)(8 * PANEL + HID + DLAT) * sizeof(float);  // 67,840 B
    cudaFuncSetAttribute(pullback_main,
                         cudaFuncAttributeMaxDynamicSharedMemorySize,
                         (int)smem_bytes);

    dim3 grid(BATCH, NCH);
    pullback_main<<<grid, NT, smem_bytes>>>(z, W1, b1, W2, b2, lth);
    loss_per_b_kernel<<<BATCH, 256>>>();
    final_reduce_kernel<<<1, 256>>>((float*)d_out);
}

// round 5
// speedup vs baseline: 1.9569x; 1.0007x over previous
#include <cuda_runtime.h>
#include <cstdint>

#define BATCH 256
#define DLAT  32
#define HID   512
#define GENES 4000
#define NCH   8
#define GC    500      // genes per chunk; 500 = 4*125 -> tg<125 owns 4 genes
#define GT    512      // U rows per block (rows 500..511 written as zeros)
#define NT    256
#define PANEL 2052     // floats per A-panel: 512*4 + 4 skew (8208 B, 16B-aligned)

// Deterministic partial-Gram buffer: [chunk][batch][32*32]
__device__ float g_gramPart[(size_t)NCH * BATCH * DLAT * DLAT];
__device__ float g_lossb[BATCH];

#define FMA2(accv, av, bv) \
    asm("fma.rn.f32x2 %0, %1, %2, %0;" : "+l"(accv) : "l"(av), "l"(bv))
#define SPLAT2(dst, s) \
    asm("mov.b64 %0, {%1,%1};" : "=l"(dst) : "r"(__float_as_uint(s)))
#define PACK2(dst, lo, hi) \
    asm("mov.b64 %0, {%1,%2};" : "=l"(dst) : "r"(__float_as_uint(lo)), "r"(__float_as_uint(hi)))

// ---------------------------------------------------------------------------
// Main kernel: one block = (batch b, gene chunk ch).
//   Phase 0: pre1/mask; masked W1 stored as 8 skewed PANELS [k][4 floats]
//            (conflict-free STS, immediate-offset broadcast LDS in phase 1).
//   Phase 1: thread (th = i-half, tg = 4 consecutive genes) computes
//            V[16 i x 4 g] with f32x2 FMA; pre2 folded in as packed FFMA2.
//   Epilogue: U = sqrt(c)*V written row-major [512][32] over the same buffer.
//   Phase 2: 32x32 SYRK with f32x2 (as R3).
// ---------------------------------------------------------------------------
__global__ void __launch_bounds__(NT, 2)
pullback_main(const float* __restrict__ z,  const float* __restrict__ W1,
              const float* __restrict__ b1, const float* __restrict__ W2,
              const float* __restrict__ b2, const float* __restrict__ lth)
{
    extern __shared__ float smem[];
    float* sW1m = smem;                  // 8 panels * PANEL floats
    float* sU   = smem;                  // [512][32] U tile (reuse)
    float* sH   = smem + 8 * PANEL;      // [512] relu(pre1)
    float* sZ   = sH + HID;              // [32]

    const int tid = threadIdx.x;
    const int b   = blockIdx.x;
    const int ch  = blockIdx.y;
    const int g0  = ch * GC;

    if (tid < DLAT) sZ[tid] = z[b * DLAT + tid];
    __syncthreads();

    // ---- Phase 0: pre1 / mask / masked W1 into panels ----
    for (int jk = 0; jk < HID / NT; ++jk) {
        const int k = tid + jk * NT;
        float wv[DLAT];
        float pre = b1[k];
        #pragma unroll
        for (int i = 0; i < DLAT; ++i) {
            wv[i] = W1[i * HID + k];          // coalesced across tid
            pre = fmaf(sZ[i], wv[i], pre);
        }
        const bool act = pre > 0.0f;
        sH[k] = act ? pre : 0.0f;
        #pragma unroll
        for (int q = 0; q < 8; ++q) {
            float4 v;
            v.x = act ? wv[4*q+0] : 0.0f;
            v.y = act ? wv[4*q+1] : 0.0f;
            v.z = act ? wv[4*q+2] : 0.0f;
            v.w = act ? wv[4*q+3] : 0.0f;
            *reinterpret_cast<float4*>(sW1m + q * PANEL + k * 4) = v;
        }
    }
    __syncthreads();

    // ---- Phase 1: 16 i (one half) x 4 consecutive genes per thread ----
    const int  th = tid & 1;               // i-half: cols th*16 .. th*16+15
    const int  tg = tid >> 1;              // gene group
    const bool gv = (tg < GC / 4);         // 125 active groups
    const int  gp = g0 + (gv ? 4 * tg : 0);

    // acc[j*8 + e]: gene j (0..3), i-pair e (0..7) within this thread's half
    unsigned long long acc[32];
    #pragma unroll
    for (int p = 0; p < 32; ++p) acc[p] = 0ULL;
    unsigned long long pr01 = 0ULL, pr23 = 0ULL;   // packed pre2 accumulators

    const float* rowp = sW1m + th * (4 * PANEL);
    const float* sHp  = sH;
    const float* w2k  = W2 + gp;

    #pragma unroll 1
    for (int k8 = 0; k8 < HID / 8; ++k8) {
        #pragma unroll
        for (int kk = 0; kk < 8; ++kk) {
            const float4 w2v =
                *reinterpret_cast<const float4*>(w2k + kk * GENES); // LDG.128
            const float hk = sHp[kk];

            unsigned long long a0, a1, a2, a3, hkp, w01, w23;
            SPLAT2(a0, w2v.x);
            SPLAT2(a1, w2v.y);
            SPLAT2(a2, w2v.z);
            SPLAT2(a3, w2v.w);
            SPLAT2(hkp, hk);
            PACK2(w01, w2v.x, w2v.y);
            PACK2(w23, w2v.z, w2v.w);
            FMA2(pr01, hkp, w01);
            FMA2(pr23, hkp, w23);

            #pragma unroll
            for (int q = 0; q < 4; ++q) {
                const ulonglong2 t = *reinterpret_cast<const ulonglong2*>(
                    rowp + q * PANEL + kk * 4);     // immediate offsets
                FMA2(acc[0*8 + 2*q],     t.x, a0);
                FMA2(acc[0*8 + 2*q + 1], t.y, a0);
                FMA2(acc[1*8 + 2*q],     t.x, a1);
                FMA2(acc[1*8 + 2*q + 1], t.y, a1);
                FMA2(acc[2*8 + 2*q],     t.x, a2);
                FMA2(acc[2*8 + 2*q + 1], t.y, a2);
                FMA2(acc[3*8 + 2*q],     t.x, a3);
                FMA2(acc[3*8 + 2*q + 1], t.y, a3);
            }
        }
        rowp += 32;          // 8 k * 4 floats
        w2k  += 8 * GENES;
        sHp  += 8;
    }

    // All warps must finish READING the panels before overwriting with U.
    __syncthreads();

    // ---- Epilogue: per-gene weight, U = sqrt(c)*V, row-major [512][32] ----
    float pr2f[4];
    {
        unsigned int l, h;
        asm("mov.b64 {%0,%1}, %2;" : "=r"(l), "=r"(h) : "l"(pr01));
        pr2f[0] = __uint_as_float(l); pr2f[1] = __uint_as_float(h);
        asm("mov.b64 {%0,%1}, %2;" : "=r"(l), "=r"(h) : "l"(pr23));
        pr2f[2] = __uint_as_float(l); pr2f[3] = __uint_as_float(h);
    }
    #pragma unroll
    for (int j = 0; j < 4; ++j) {
        const int row = 4 * tg + j;            // rows 500..511 get sc=0 zeros
        float sc = 0.0f;
        if (gv) {
            const int g = gp + j;
            const float x  = pr2f[j] + b2[g];
            const float mu = (x > 0.f) ? (x + log1pf(__expf(-x)))
                                       : log1pf(__expf(x));
            const float sg = 1.0f / (1.0f + __expf(-x));
            const float thv = __expf(lth[g]);
            const float wt = thv / fmaf(mu, mu + thv, 1e-6f);
            sc = sg * sqrtf(wt);
        }
        float* urow = sU + row * DLAT + th * 16;
        #pragma unroll
        for (int q = 0; q < 4; ++q) {
            unsigned int l0, h0, l1, h1;
            asm("mov.b64 {%0,%1}, %2;" : "=r"(l0), "=r"(h0) : "l"(acc[j*8 + 2*q]));
            asm("mov.b64 {%0,%1}, %2;" : "=r"(l1), "=r"(h1) : "l"(acc[j*8 + 2*q + 1]));
            float4 v;
            v.x = sc * __uint_as_float(l0);
            v.y = sc * __uint_as_float(h0);
            v.z = sc * __uint_as_float(l1);
            v.w = sc * __uint_as_float(h1);
            *reinterpret_cast<float4*>(urow + (q << 2)) = v;
        }
    }
    __syncthreads();

    // ---- Phase 2: Gram partial = U U^T, f32x2, 2x2 tile per thread ----
    const int ti = tid & 15;        // i0 = 2*ti
    const int tj = tid >> 4;        // j0 = 2*tj
    const float* pa = sU + 2 * ti;
    const float* pb = sU + 2 * tj;
    unsigned long long ga0 = 0ULL, ga1 = 0ULL;  // rows i0, i0+1 x cols {j0,j0+1}

    #pragma unroll 1
    for (int g8 = 0; g8 < GT / 8; ++g8) {
        #pragma unroll
        for (int s = 0; s < 8; ++s) {
            const unsigned long long avu =
                *reinterpret_cast<const unsigned long long*>(pa + s * DLAT);
            const unsigned long long bvu =
                *reinterpret_cast<const unsigned long long*>(pb + s * DLAT);
            unsigned int alo, ahi;
            asm("mov.b64 {%0,%1}, %2;" : "=r"(alo), "=r"(ahi) : "l"(avu));
            unsigned long long ad0, ad1;
            asm("mov.b64 %0, {%1,%1};" : "=l"(ad0) : "r"(alo));
            asm("mov.b64 %0, {%1,%1};" : "=l"(ad1) : "r"(ahi));
            FMA2(ga0, ad0, bvu);
            FMA2(ga1, ad1, bvu);
        }
        pa += 8 * DLAT;
        pb += 8 * DLAT;
    }

    float* dst = g_gramPart + ((size_t)ch * BATCH + b) * (DLAT * DLAT);
    {
        unsigned int l0, h0, l1, h1;
        asm("mov.b64 {%0,%1}, %2;" : "=r"(l0), "=r"(h0) : "l"(ga0));
        asm("mov.b64 {%0,%1}, %2;" : "=r"(l1), "=r"(h1) : "l"(ga1));
        dst[(2*ti    ) * DLAT + 2*tj    ] = __uint_as_float(l0);
        dst[(2*ti    ) * DLAT + 2*tj + 1] = __uint_as_float(h0);
        dst[(2*ti + 1) * DLAT + 2*tj    ] = __uint_as_float(l1);
        dst[(2*ti + 1) * DLAT + 2*tj + 1] = __uint_as_float(h1);
    }
}

// ---------------------------------------------------------------------------
// Per-batch loss: sum_ij (sum_ch Gram_partial - I)^2  (deterministic)
// ---------------------------------------------------------------------------
__global__ void __launch_bounds__(256)
loss_per_b_kernel()
{
    const int b = blockIdx.x;
    const int t = threadIdx.x;
    float accl = 0.0f;
    #pragma unroll
    for (int r = 0; r < 4; ++r) {
        const int ij = t + r * 256;
        float s = 0.0f;
        #pragma unroll
        for (int c = 0; c < NCH; ++c)
            s += g_gramPart[((size_t)c * BATCH + b) * 1024 + ij];
        if (ij % 33 == 0) s -= 1.0f;   // ALPHA * I on the diagonal
        accl = fmaf(s, s, accl);
    }
    __shared__ float red[256];
    red[t] = accl;
    __syncthreads();
    for (int o = 128; o > 0; o >>= 1) {
        if (t < o) red[t] += red[t + o];
        __syncthreads();
    }
    if (t == 0) g_lossb[b] = red[0];
}

__global__ void __launch_bounds__(256)
final_reduce_kernel(float* __restrict__ out)
{
    const int t = threadIdx.x;
    __shared__ float red[256];
    red[t] = g_lossb[t];
    __syncthreads();
    for (int o = 128; o > 0; o >>= 1) {
        if (t < o) red[t] += red[t + o];
        __syncthreads();
    }
    if (t == 0) out[0] = red[0] * (1.0f / (float)BATCH);
}

// ---------------------------------------------------------------------------
extern "C" void kernel_launch(void* const* d_in, const int* in_sizes, int n_in,
                              void* d_out, int out_size)
{
    const float* z   = (const float*)d_in[0];
    const float* W1  = (const float*)d_in[1];
    const float* b1  = (const float*)d_in[2];
    const float* W2  = (const float*)d_in[3];
    const float* b2  = (const float*)d_in[4];
    const float* lth = (const float*)d_in[5];

    const size_t smem_bytes =
        (size_t)(8 * PANEL + HID + DLAT) * sizeof(float);  // 67,840 B
    cudaFuncSetAttribute(pullback_main,
                         cudaFuncAttributeMaxDynamicSharedMemorySize,
                         (int)smem_bytes);

    dim3 grid(BATCH, NCH);
    pullback_main<<<grid, NT, smem_bytes>>>(z, W1, b1, W2, b2, lth);
    loss_per_b_kernel<<<BATCH, 256>>>();
    final_reduce_kernel<<<1, 256>>>((float*)d_out);
}

// round 6
// speedup vs baseline: 2.0279x; 1.0363x over previous
#include <cuda_runtime.h>
#include <cstdint>

#define BATCH 256
#define DLAT  32
#define HID   512
#define GENES 4000
#define NCH   8
#define GC    500      // genes per chunk; 500 = 4*125 -> tg<125 owns 4 genes
#define GT    512      // U rows per block (rows 500..511 written as zeros)
#define NT    256
#define PANEL 2052     // floats per A-panel: 512*4 + 4 skew (8208 B, 16B-aligned)

// Deterministic partial-Gram buffer: [chunk][batch][32*32]
__device__ float g_gramPart[(size_t)NCH * BATCH * DLAT * DLAT];
__device__ float g_lossb[BATCH];

#define FMA2(accv, av, bv) \
    asm("fma.rn.f32x2 %0, %1, %2, %0;" : "+l"(accv) : "l"(av), "l"(bv))
#define SPLAT2(dst, s) \
    asm("mov.b64 %0, {%1,%1};" : "=l"(dst) : "r"(__float_as_uint(s)))
#define PACK2(dst, lo, hi) \
    asm("mov.b64 %0, {%1,%2};" : "=l"(dst) : "r"(__float_as_uint(lo)), "r"(__float_as_uint(hi)))

// ---------------------------------------------------------------------------
// Main kernel: one block = (batch b, gene chunk ch).
//   Phase 0: pre1/mask; masked W1 stored as 8 skewed PANELS [k][4 floats].
//   Phase 1: thread (th = i-half, tg = 4 consecutive genes) computes
//            V[16 i x 4 g] with f32x2 FMA. W2 rows are DOUBLE-BUFFERED in
//            registers at 4-k granularity so the LDG latency is hidden.
//   Epilogue: U = sqrt(c)*V written row-major [512][32] over the same buffer.
//   Phase 2: 32x32 SYRK with f32x2.
// ---------------------------------------------------------------------------
__global__ void __launch_bounds__(NT, 2)
pullback_main(const float* __restrict__ z,  const float* __restrict__ W1,
              const float* __restrict__ b1, const float* __restrict__ W2,
              const float* __restrict__ b2, const float* __restrict__ lth)
{
    extern __shared__ float smem[];
    float* sW1m = smem;                  // 8 panels * PANEL floats
    float* sU   = smem;                  // [512][32] U tile (reuse)
    float* sH   = smem + 8 * PANEL;      // [512] relu(pre1)
    float* sZ   = sH + HID;              // [32]

    const int tid = threadIdx.x;
    const int b   = blockIdx.x;
    const int ch  = blockIdx.y;
    const int g0  = ch * GC;

    if (tid < DLAT) sZ[tid] = z[b * DLAT + tid];
    __syncthreads();

    // ---- Phase 0: pre1 / mask / masked W1 into panels ----
    for (int jk = 0; jk < HID / NT; ++jk) {
        const int k = tid + jk * NT;
        float wv[DLAT];
        float pre = b1[k];
        #pragma unroll
        for (int i = 0; i < DLAT; ++i) {
            wv[i] = W1[i * HID + k];          // coalesced across tid
            pre = fmaf(sZ[i], wv[i], pre);
        }
        const bool act = pre > 0.0f;
        sH[k] = act ? pre : 0.0f;
        #pragma unroll
        for (int q = 0; q < 8; ++q) {
            float4 v;
            v.x = act ? wv[4*q+0] : 0.0f;
            v.y = act ? wv[4*q+1] : 0.0f;
            v.z = act ? wv[4*q+2] : 0.0f;
            v.w = act ? wv[4*q+3] : 0.0f;
            *reinterpret_cast<float4*>(sW1m + q * PANEL + k * 4) = v;
        }
    }
    __syncthreads();

    // ---- Phase 1: 16 i (one half) x 4 consecutive genes per thread ----
    const int  th = tid & 1;               // i-half: cols th*16 .. th*16+15
    const int  tg = tid >> 1;              // gene group
    const bool gv = (tg < GC / 4);         // 125 active groups
    const int  gp = g0 + (gv ? 4 * tg : 0);

    // acc[j*8 + e]: gene j (0..3), i-pair e (0..7) within this thread's half
    unsigned long long acc[32];
    #pragma unroll
    for (int p = 0; p < 32; ++p) acc[p] = 0ULL;
    unsigned long long pr01 = 0ULL, pr23 = 0ULL;   // packed pre2 accumulators

    const float* rowp = sW1m + th * (4 * PANEL);
    const float* sHp  = sH;
    const float* w2k  = W2 + gp;

    // Preload W2 group 0 (k = 0..3)
    float4 wcur[4];
    #pragma unroll
    for (int kk = 0; kk < 4; ++kk)
        wcur[kk] = *reinterpret_cast<const float4*>(w2k + kk * GENES);
    w2k += 4 * GENES;

    #pragma unroll 2
    for (int k4 = 0; k4 < HID / 4; ++k4) {
        // Prefetch NEXT 4-k group (clamped re-read of the last valid group
        // on the final iteration; values never used).
        const float* wnp = (k4 < HID / 4 - 1) ? w2k : (w2k - 4 * GENES);
        float4 wnxt[4];
        #pragma unroll
        for (int kk = 0; kk < 4; ++kk)
            wnxt[kk] = *reinterpret_cast<const float4*>(wnp + kk * GENES);
        w2k += 4 * GENES;

        const float4 hv = *reinterpret_cast<const float4*>(sHp);  // LDS.128
        const float hks[4] = {hv.x, hv.y, hv.z, hv.w};

        #pragma unroll
        for (int kk = 0; kk < 4; ++kk) {
            const float4 w2v = wcur[kk];
            unsigned long long a0, a1, a2, a3, hkp, w01, w23;
            SPLAT2(a0, w2v.x);
            SPLAT2(a1, w2v.y);
            SPLAT2(a2, w2v.z);
            SPLAT2(a3, w2v.w);
            SPLAT2(hkp, hks[kk]);
            PACK2(w01, w2v.x, w2v.y);
            PACK2(w23, w2v.z, w2v.w);
            FMA2(pr01, hkp, w01);
            FMA2(pr23, hkp, w23);

            #pragma unroll
            for (int q = 0; q < 4; ++q) {
                const ulonglong2 t = *reinterpret_cast<const ulonglong2*>(
                    rowp + q * PANEL + kk * 4);     // immediate offsets
                FMA2(acc[0*8 + 2*q],     t.x, a0);
                FMA2(acc[0*8 + 2*q + 1], t.y, a0);
                FMA2(acc[1*8 + 2*q],     t.x, a1);
                FMA2(acc[1*8 + 2*q + 1], t.y, a1);
                FMA2(acc[2*8 + 2*q],     t.x, a2);
                FMA2(acc[2*8 + 2*q + 1], t.y, a2);
                FMA2(acc[3*8 + 2*q],     t.x, a3);
                FMA2(acc[3*8 + 2*q + 1], t.y, a3);
            }
        }

        #pragma unroll
        for (int kk = 0; kk < 4; ++kk) wcur[kk] = wnxt[kk];
        rowp += 16;          // 4 k * 4 floats
        sHp  += 4;
    }

    // All warps must finish READING the panels before overwriting with U.
    __syncthreads();

    // ---- Epilogue: per-gene weight, U = sqrt(c)*V, row-major [512][32] ----
    float pr2f[4];
    {
        unsigned int l, h;
        asm("mov.b64 {%0,%1}, %2;" : "=r"(l), "=r"(h) : "l"(pr01));
        pr2f[0] = __uint_as_float(l); pr2f[1] = __uint_as_float(h);
        asm("mov.b64 {%0,%1}, %2;" : "=r"(l), "=r"(h) : "l"(pr23));
        pr2f[2] = __uint_as_float(l); pr2f[3] = __uint_as_float(h);
    }
    #pragma unroll
    for (int j = 0; j < 4; ++j) {
        const int row = 4 * tg + j;            // rows 500..511 get sc=0 zeros
        float sc = 0.0f;
        if (gv) {
            const int g = gp + j;
            const float x  = pr2f[j] + b2[g];
            const float mu = (x > 0.f) ? (x + log1pf(__expf(-x)))
                                       : log1pf(__expf(x));
            const float sg = 1.0f / (1.0f + __expf(-x));
            const float thv = __expf(lth[g]);
            const float wt = thv / fmaf(mu, mu + thv, 1e-6f);
            sc = sg * sqrtf(wt);
        }
        float* urow = sU + row * DLAT + th * 16;
        #pragma unroll
        for (int q = 0; q < 4; ++q) {
            unsigned int l0, h0, l1, h1;
            asm("mov.b64 {%0,%1}, %2;" : "=r"(l0), "=r"(h0) : "l"(acc[j*8 + 2*q]));
            asm("mov.b64 {%0,%1}, %2;" : "=r"(l1), "=r"(h1) : "l"(acc[j*8 + 2*q + 1]));
            float4 v;
            v.x = sc * __uint_as_float(l0);
            v.y = sc * __uint_as_float(h0);
            v.z = sc * __uint_as_float(l1);
            v.w = sc * __uint_as_float(h1);
            *reinterpret_cast<float4*>(urow + (q << 2)) = v;
        }
    }
    __syncthreads();

    // ---- Phase 2: Gram partial = U U^T, f32x2, 2x2 tile per thread ----
    const int ti = tid & 15;        // i0 = 2*ti
    const int tj = tid >> 4;        // j0 = 2*tj
    const float* pa = sU + 2 * ti;
    const float* pb = sU + 2 * tj;
    unsigned long long ga0 = 0ULL, ga1 = 0ULL;  // rows i0, i0+1 x cols {j0,j0+1}

    #pragma unroll 1
    for (int g8 = 0; g8 < GT / 8; ++g8) {
        #pragma unroll
        for (int s = 0; s < 8; ++s) {
            const unsigned long long avu =
                *reinterpret_cast<const unsigned long long*>(pa + s * DLAT);
            const unsigned long long bvu =
                *reinterpret_cast<const unsigned long long*>(pb + s * DLAT);
            unsigned int alo, ahi;
            asm("mov.b64 {%0,%1}, %2;" : "=r"(alo), "=r"(ahi) : "l"(avu));
            unsigned long long ad0, ad1;
            asm("mov.b64 %0, {%1,%1};" : "=l"(ad0) : "r"(alo));
            asm("mov.b64 %0, {%1,%1};" : "=l"(ad1) : "r"(ahi));
            FMA2(ga0, ad0, bvu);
            FMA2(ga1, ad1, bvu);
        }
        pa += 8 * DLAT;
        pb += 8 * DLAT;
    }

    float* dst = g_gramPart + ((size_t)ch * BATCH + b) * (DLAT * DLAT);
    {
        unsigned int l0, h0, l1, h1;
        asm("mov.b64 {%0,%1}, %2;" : "=r"(l0), "=r"(h0) : "l"(ga0));
        asm("mov.b64 {%0,%1}, %2;" : "=r"(l1), "=r"(h1) : "l"(ga1));
        dst[(2*ti    ) * DLAT + 2*tj    ] = __uint_as_float(l0);
        dst[(2*ti    ) * DLAT + 2*tj + 1] = __uint_as_float(h0);
        dst[(2*ti + 1) * DLAT + 2*tj    ] = __uint_as_float(l1);
        dst[(2*ti + 1) * DLAT + 2*tj + 1] = __uint_as_float(h1);
    }
}

// ---------------------------------------------------------------------------
// Per-batch loss: sum_ij (sum_ch Gram_partial - I)^2  (deterministic)
// ---------------------------------------------------------------------------
__global__ void __launch_bounds__(256)
loss_per_b_kernel()
{
    const int b = blockIdx.x;
    const int t = threadIdx.x;
    float accl = 0.0f;
    #pragma unroll
    for (int r = 0; r < 4; ++r) {
        const int ij = t + r * 256;
        float s = 0.0f;
        #pragma unroll
        for (int c = 0; c < NCH; ++c)
            s += g_gramPart[((size_t)c * BATCH + b) * 1024 + ij];
        if (ij % 33 == 0) s -= 1.0f;   // ALPHA * I on the diagonal
        accl = fmaf(s, s, accl);
    }
    __shared__ float red[256];
    red[t] = accl;
    __syncthreads();
    for (int o = 128; o > 0; o >>= 1) {
        if (t < o) red[t] += red[t + o];
        __syncthreads();
    }
    if (t == 0) g_lossb[b] = red[0];
}

__global__ void __launch_bounds__(256)
final_reduce_kernel(float* __restrict__ out)
{
    const int t = threadIdx.x;
    __shared__ float red[256];
    red[t] = g_lossb[t];
    __syncthreads();
    for (int o = 128; o > 0; o >>= 1) {
        if (t < o) red[t] += red[t + o];
        __syncthreads();
    }
    if (t == 0) out[0] = red[0] * (1.0f / (float)BATCH);
}

// ---------------------------------------------------------------------------
extern "C" void kernel_launch(void* const* d_in, const int* in_sizes, int n_in,
                              void* d_out, int out_size)
{
    const float* z   = (const float*)d_in[0];
    const float* W1  = (const float*)d_in[1];
    const float* b1  = (const float*)d_in[2];
    const float* W2  = (const float*)d_in[3];
    const float* b2  = (const float*)d_in[4];
    const float* lth = (const float*)d_in[5];

    const size_t smem_bytes =
        (size_t)(8 * PANEL + HID + DLAT) * sizeof(float);  // 67,840 B
    cudaFuncSetAttribute(pullback_main,
                         cudaFuncAttributeMaxDynamicSharedMemorySize,
                         (int)smem_bytes);

    dim3 grid(BATCH, NCH);
    pullback_main<<<grid, NT, smem_bytes>>>(z, W1, b1, W2, b2, lth);
    loss_per_b_kernel<<<BATCH, 256>>>();
    final_reduce_kernel<<<1, 256>>>((float*)d_out);
}